// round 14
// baseline (speedup 1.0000x reference)
#include <cuda_runtime.h>
#include <cstdint>

#define N_NODES 100000
#define D_FEAT 32
#define N_EDGES 2000000
#define EPS 1e-8f
#define LMAX 96   // ELL stride; Poisson(20) max deg over 100k nodes ~47, P(>=96) ~ 1e-30

#define TB 256
#define FILL_BLOCKS ((N_EDGES / 8 + TB - 1) / TB)        // 977 (8 edges/thread)
#define RNORM_BLOCKS ((N_NODES * 8 + TB - 1) / TB)       // 3125 (8 lanes/node)

// ---------------- scratch (static device globals; no allocs allowed) ----------------
__device__ float g_rnorm[N_NODES];          // 1/||x_n|| per node (400 KB, L2-resident)
__device__ int   g_cursor[N_NODES];         // fill cursor == in-degree after fill
__device__ int   g_ell[N_NODES * LMAX];     // ELL: src node per slot (38.4 MB)

// ---------------- phase 1: heterogeneous rnorm + ELL fill (independent work) ----------------
__global__ void k_pre(const float* __restrict__ x,
                      const int* __restrict__ esrc,
                      const int* __restrict__ edst) {
    if (blockIdx.x < FILL_BLOCKS) {
        // ---- fill: 8 edges per thread for MLP ----
        int t  = blockIdx.x * TB + threadIdx.x;
        int e0 = t * 8;
        if (e0 >= N_EDGES) return;
        int4 da = __ldg((const int4*)(edst + e0));
        int4 db = __ldg((const int4*)(edst + e0) + 1);
        int4 sa = __ldg((const int4*)(esrc + e0));
        int4 sb = __ldg((const int4*)(esrc + e0) + 1);
        int p0 = atomicAdd(&g_cursor[da.x], 1);
        int p1 = atomicAdd(&g_cursor[da.y], 1);
        int p2 = atomicAdd(&g_cursor[da.z], 1);
        int p3 = atomicAdd(&g_cursor[da.w], 1);
        int p4 = atomicAdd(&g_cursor[db.x], 1);
        int p5 = atomicAdd(&g_cursor[db.y], 1);
        int p6 = atomicAdd(&g_cursor[db.z], 1);
        int p7 = atomicAdd(&g_cursor[db.w], 1);
        if (p0 < LMAX) g_ell[da.x * LMAX + p0] = sa.x;
        if (p1 < LMAX) g_ell[da.y * LMAX + p1] = sa.y;
        if (p2 < LMAX) g_ell[da.z * LMAX + p2] = sa.z;
        if (p3 < LMAX) g_ell[da.w * LMAX + p3] = sa.w;
        if (p4 < LMAX) g_ell[db.x * LMAX + p4] = sb.x;
        if (p5 < LMAX) g_ell[db.y * LMAX + p5] = sb.y;
        if (p6 < LMAX) g_ell[db.z * LMAX + p6] = sb.z;
        if (p7 < LMAX) g_ell[db.w * LMAX + p7] = sb.w;
    } else {
        // ---- rnorm: 8-lane group per node ----
        int tid  = (blockIdx.x - FILL_BLOCKS) * TB + threadIdx.x;
        int node = tid >> 3;
        int gl   = tid & 7;
        if (node >= N_NODES) return;
        float4 v = __ldg((const float4*)(x + (size_t)node * D_FEAT) + gl);
        float s = v.x * v.x + v.y * v.y + v.z * v.z + v.w * v.w;
        #pragma unroll
        for (int o = 4; o; o >>= 1) s += __shfl_xor_sync(0xFFFFFFFFu, s, o);
        if (gl == 0) g_rnorm[node] = rsqrtf(s + EPS);
    }
}

// ---------------- phase 2: fused dot + exp + accumulate + normalize ----------------
// Warp per dst node; 8 edge groups of 4 lanes; lane owns 8 features (2x float4).
// out_i = (sum_j ev_j * x_j) / (sum_j ev_j + EPS), ev_j = exp(beta * <x^_i, x^_j>).
// Max-subtraction skipped: |logit| <= 1 (beta in [0,1), cos in [-1,1]), exp in
// [0.37, 2.72]; softmax is shift-invariant (EPS scaling differs by <=1e-8 rel).
// launch_bounds(128,12): cap regs at 42 -> 48 resident warps (was 56 regs / 36 warps).
__global__ void __launch_bounds__(128, 12)
k_fused(const float* __restrict__ x,
        const float* __restrict__ beta,
        float* __restrict__ out) {
    int tid   = blockIdx.x * blockDim.x + threadIdx.x;
    int node  = tid >> 5;
    int lane  = tid & 31;
    int group = lane >> 2;       // 0..7: edge slot within iteration
    int gl    = lane & 3;        // 0..3: 8-float chunk within row
    if (node >= N_NODES) return;

    float bl2 = __ldg(beta) * 1.44269504f;               // beta * log2(e)
    float rn  = __ldg(g_rnorm + node);
    const float4* xrow = (const float4*)(x + (size_t)node * D_FEAT);
    float4 xd0 = __ldg(xrow + gl * 2);
    float4 xd1 = __ldg(xrow + gl * 2 + 1);
    float4 xh0 = make_float4(xd0.x * rn, xd0.y * rn, xd0.z * rn, xd0.w * rn);
    float4 xh1 = make_float4(xd1.x * rn, xd1.y * rn, xd1.z * rn, xd1.w * rn);

    int deg   = min(g_cursor[node], LMAX);
    int iters = (deg + 7) >> 3;
    const int* ell = g_ell + (size_t)node * LMAX;

    float4 acc0 = make_float4(0.f, 0.f, 0.f, 0.f);
    float4 acc1 = make_float4(0.f, 0.f, 0.f, 0.f);
    float  ss   = 0.0f;

    for (int it = 0; it < iters; it++) {
        int slot  = it * 8 + group;
        int valid = slot < deg;
        int s = valid ? __ldg(ell + slot) : 0;                 // 4-lane broadcast
        const float4* srow = (const float4*)(x + (size_t)s * D_FEAT);
        float4 xs0 = __ldg(srow + gl * 2);                     // 2 independent 16B loads
        float4 xs1 = __ldg(srow + gl * 2 + 1);
        float rs = __ldg(g_rnorm + s);
        float p = xh0.x * xs0.x + xh0.y * xs0.y + xh0.z * xs0.z + xh0.w * xs0.w
                + xh1.x * xs1.x + xh1.y * xs1.y + xh1.z * xs1.z + xh1.w * xs1.w;
        // reduce dot over the 4 lanes of this group (one shfl serves all 8 groups)
        p += __shfl_xor_sync(0xFFFFFFFFu, p, 1);
        p += __shfl_xor_sync(0xFFFFFFFFu, p, 2);
        float ev = valid ? exp2f(bl2 * p * rs) : 0.0f;
        acc0.x += ev * xs0.x; acc0.y += ev * xs0.y;
        acc0.z += ev * xs0.z; acc0.w += ev * xs0.w;
        acc1.x += ev * xs1.x; acc1.y += ev * xs1.y;
        acc1.z += ev * xs1.z; acc1.w += ev * xs1.w;
        ss += ev;
    }

    // combine the 8 groups (xor 4/8/16 preserves gl = lane&3)
    #pragma unroll
    for (int o = 4; o < 32; o <<= 1) {
        acc0.x += __shfl_xor_sync(0xFFFFFFFFu, acc0.x, o);
        acc0.y += __shfl_xor_sync(0xFFFFFFFFu, acc0.y, o);
        acc0.z += __shfl_xor_sync(0xFFFFFFFFu, acc0.z, o);
        acc0.w += __shfl_xor_sync(0xFFFFFFFFu, acc0.w, o);
        acc1.x += __shfl_xor_sync(0xFFFFFFFFu, acc1.x, o);
        acc1.y += __shfl_xor_sync(0xFFFFFFFFu, acc1.y, o);
        acc1.z += __shfl_xor_sync(0xFFFFFFFFu, acc1.z, o);
        acc1.w += __shfl_xor_sync(0xFFFFFFFFu, acc1.w, o);
        ss     += __shfl_xor_sync(0xFFFFFFFFu, ss, o);
    }

    if (lane < 4) {                                      // group 0 stores the row
        float inv = 1.0f / (ss + EPS);
        float4* orow = (float4*)(out + (size_t)node * D_FEAT);
        orow[gl * 2 + 0] = make_float4(acc0.x * inv, acc0.y * inv, acc0.z * inv, acc0.w * inv);
        orow[gl * 2 + 1] = make_float4(acc1.x * inv, acc1.y * inv, acc1.z * inv, acc1.w * inv);
    }
}

// ---------------- launch ----------------
extern "C" void kernel_launch(void* const* d_in, const int* in_sizes, int n_in,
                              void* d_out, int out_size) {
    const float* x    = (const float*)d_in[0];
    const float* beta = (const float*)d_in[1];
    const int*   ei   = (const int*)d_in[2];   // [2, E] row-major, int32
    const int*   esrc = ei;
    const int*   edst = ei + N_EDGES;
    float* out = (float*)d_out;

    // zero fill cursors (graph-legal memset node)
    void* cur_ptr = nullptr;
    cudaGetSymbolAddress(&cur_ptr, g_cursor);
    cudaMemsetAsync(cur_ptr, 0, N_NODES * sizeof(int));

    const int TBF = 128;
    const int gridF = (N_NODES * 32 + TBF - 1) / TBF;   // warp per node

    k_pre<<<FILL_BLOCKS + RNORM_BLOCKS, TB>>>(x, esrc, edst);
    k_fused<<<gridF, TBF>>>(x, beta, out);
}

// round 15
// speedup vs baseline: 1.1471x; 1.1471x over previous
#include <cuda_runtime.h>
#include <cstdint>

#define N_NODES 100000
#define D_FEAT 32
#define N_EDGES 2000000
#define EPS 1e-8f
#define LMAX 96   // ELL stride; Poisson(20) max deg over 100k nodes ~47, P(>=96) ~ 1e-30

#define TB 256
#define FILL_BLOCKS ((N_EDGES / 4 + TB - 1) / TB)        // 1954 (4 edges/thread)
#define RNORM_BLOCKS ((N_NODES * 8 + TB - 1) / TB)       // 3125 (8 lanes/node)

// ---------------- scratch (static device globals; no allocs allowed) ----------------
__device__ float g_rnorm[N_NODES];          // 1/||x_n|| per node (400 KB, L2-resident)
__device__ int   g_cursor[N_NODES];         // fill cursor == in-degree after fill
__device__ int   g_ell[N_NODES * LMAX];     // ELL: src node per slot (38.4 MB)

// ---------------- phase 1: heterogeneous rnorm + ELL fill (independent work) ----------------
__global__ void k_pre(const float* __restrict__ x,
                      const int* __restrict__ esrc,
                      const int* __restrict__ edst) {
    if (blockIdx.x < FILL_BLOCKS) {
        // ---- fill: 4 edges per thread for MLP ----
        int t  = blockIdx.x * TB + threadIdx.x;
        int e0 = t * 4;
        if (e0 >= N_EDGES) return;
        int4 d4 = __ldg((const int4*)(edst + e0));
        int4 s4 = __ldg((const int4*)(esrc + e0));
        int p0 = atomicAdd(&g_cursor[d4.x], 1);
        int p1 = atomicAdd(&g_cursor[d4.y], 1);
        int p2 = atomicAdd(&g_cursor[d4.z], 1);
        int p3 = atomicAdd(&g_cursor[d4.w], 1);
        if (p0 < LMAX) g_ell[d4.x * LMAX + p0] = s4.x;
        if (p1 < LMAX) g_ell[d4.y * LMAX + p1] = s4.y;
        if (p2 < LMAX) g_ell[d4.z * LMAX + p2] = s4.z;
        if (p3 < LMAX) g_ell[d4.w * LMAX + p3] = s4.w;
    } else {
        // ---- rnorm: 8-lane group per node ----
        int tid  = (blockIdx.x - FILL_BLOCKS) * TB + threadIdx.x;
        int node = tid >> 3;
        int gl   = tid & 7;
        if (node >= N_NODES) return;
        float4 v = __ldg((const float4*)(x + (size_t)node * D_FEAT) + gl);
        float s = v.x * v.x + v.y * v.y + v.z * v.z + v.w * v.w;
        #pragma unroll
        for (int o = 4; o; o >>= 1) s += __shfl_xor_sync(0xFFFFFFFFu, s, o);
        if (gl == 0) g_rnorm[node] = rsqrtf(s + EPS);
    }
}

// ---------------- phase 2: fused dot + exp + accumulate + normalize ----------------
// Warp per dst node; 8 edge groups of 4 lanes; lane owns 8 features (2x float4).
// The full 96-entry ELL row is preloaded into 3 regs/lane (3 coalesced 128B loads)
// and indices are distributed in-loop by one SHFL.IDX — the per-iteration
// ell-load -> row-load L2 serialization is gone, so row loads of successive
// iterations overlap.
// out_i = (sum_j ev_j * x_j) / (sum_j ev_j + EPS), ev_j = exp(beta * <x^_i, x^_j>).
// Max-subtraction skipped: |logit| <= 1 (beta in [0,1), cos in [-1,1]), exp in
// [0.37, 2.72]; softmax is shift-invariant (EPS scaling differs by <=1e-8 rel).
__global__ void __launch_bounds__(128, 9)   // 56-reg budget = R13's no-spill point
k_fused(const float* __restrict__ x,
        const float* __restrict__ beta,
        float* __restrict__ out) {
    int tid   = blockIdx.x * blockDim.x + threadIdx.x;
    int node  = tid >> 5;
    int lane  = tid & 31;
    int group = lane >> 2;       // 0..7: edge slot within iteration
    int gl    = lane & 3;        // 0..3: 8-float chunk within row
    if (node >= N_NODES) return;

    const int* ell = g_ell + (size_t)node * LMAX;
    // preload entire ELL row: slots [0,32), [32,64), [64,96)
    int i0 = __ldg(ell + lane);
    int i1 = __ldg(ell + 32 + lane);
    int i2 = __ldg(ell + 64 + lane);

    float bl2 = __ldg(beta) * 1.44269504f;               // beta * log2(e)
    float rn  = __ldg(g_rnorm + node);
    const float4* xrow = (const float4*)(x + (size_t)node * D_FEAT);
    float4 xd0 = __ldg(xrow + gl * 2);
    float4 xd1 = __ldg(xrow + gl * 2 + 1);
    float4 xh0 = make_float4(xd0.x * rn, xd0.y * rn, xd0.z * rn, xd0.w * rn);
    float4 xh1 = make_float4(xd1.x * rn, xd1.y * rn, xd1.z * rn, xd1.w * rn);

    int deg   = min(g_cursor[node], LMAX);
    int iters = (deg + 7) >> 3;

    float4 acc0 = make_float4(0.f, 0.f, 0.f, 0.f);
    float4 acc1 = make_float4(0.f, 0.f, 0.f, 0.f);
    float  ss   = 0.0f;

    #pragma unroll 2
    for (int it = 0; it < iters; it++) {
        int slot  = it * 8 + group;
        int valid = slot < deg;
        int reg   = it >> 2;                 // warp-uniform: which preload reg holds slot
        int hold  = (reg == 0) ? i0 : ((reg == 1) ? i1 : i2);
        int s     = __shfl_sync(0xFFFFFFFFu, hold, slot & 31);
        s = valid ? s : 0;
        const float4* srow = (const float4*)(x + (size_t)s * D_FEAT);
        float4 xs0 = __ldg(srow + gl * 2);                     // 2 independent 16B loads
        float4 xs1 = __ldg(srow + gl * 2 + 1);
        float rs = __ldg(g_rnorm + s);
        float p = xh0.x * xs0.x + xh0.y * xs0.y + xh0.z * xs0.z + xh0.w * xs0.w
                + xh1.x * xs1.x + xh1.y * xs1.y + xh1.z * xs1.z + xh1.w * xs1.w;
        // reduce dot over the 4 lanes of this group (one shfl serves all 8 groups)
        p += __shfl_xor_sync(0xFFFFFFFFu, p, 1);
        p += __shfl_xor_sync(0xFFFFFFFFu, p, 2);
        float ev = valid ? exp2f(bl2 * p * rs) : 0.0f;
        acc0.x += ev * xs0.x; acc0.y += ev * xs0.y;
        acc0.z += ev * xs0.z; acc0.w += ev * xs0.w;
        acc1.x += ev * xs1.x; acc1.y += ev * xs1.y;
        acc1.z += ev * xs1.z; acc1.w += ev * xs1.w;
        ss += ev;
    }

    // combine the 8 groups (xor 4/8/16 preserves gl = lane&3)
    #pragma unroll
    for (int o = 4; o < 32; o <<= 1) {
        acc0.x += __shfl_xor_sync(0xFFFFFFFFu, acc0.x, o);
        acc0.y += __shfl_xor_sync(0xFFFFFFFFu, acc0.y, o);
        acc0.z += __shfl_xor_sync(0xFFFFFFFFu, acc0.z, o);
        acc0.w += __shfl_xor_sync(0xFFFFFFFFu, acc0.w, o);
        acc1.x += __shfl_xor_sync(0xFFFFFFFFu, acc1.x, o);
        acc1.y += __shfl_xor_sync(0xFFFFFFFFu, acc1.y, o);
        acc1.z += __shfl_xor_sync(0xFFFFFFFFu, acc1.z, o);
        acc1.w += __shfl_xor_sync(0xFFFFFFFFu, acc1.w, o);
        ss     += __shfl_xor_sync(0xFFFFFFFFu, ss, o);
    }

    if (lane < 4) {                                      // group 0 stores the row
        float inv = 1.0f / (ss + EPS);
        float4* orow = (float4*)(out + (size_t)node * D_FEAT);
        orow[gl * 2 + 0] = make_float4(acc0.x * inv, acc0.y * inv, acc0.z * inv, acc0.w * inv);
        orow[gl * 2 + 1] = make_float4(acc1.x * inv, acc1.y * inv, acc1.z * inv, acc1.w * inv);
    }
}

// ---------------- launch ----------------
extern "C" void kernel_launch(void* const* d_in, const int* in_sizes, int n_in,
                              void* d_out, int out_size) {
    const float* x    = (const float*)d_in[0];
    const float* beta = (const float*)d_in[1];
    const int*   ei   = (const int*)d_in[2];   // [2, E] row-major, int32
    const int*   esrc = ei;
    const int*   edst = ei + N_EDGES;
    float* out = (float*)d_out;

    // zero fill cursors (graph-legal memset node)
    void* cur_ptr = nullptr;
    cudaGetSymbolAddress(&cur_ptr, g_cursor);
    cudaMemsetAsync(cur_ptr, 0, N_NODES * sizeof(int));

    const int TBF = 128;
    const int gridF = (N_NODES * 32 + TBF - 1) / TBF;   // warp per node

    k_pre<<<FILL_BLOCKS + RNORM_BLOCKS, TB>>>(x, esrc, edst);
    k_fused<<<gridF, TBF>>>(x, beta, out);
}

// round 16
// speedup vs baseline: 1.1653x; 1.0159x over previous
#include <cuda_runtime.h>
#include <cstdint>

#define N_NODES 100000
#define D_FEAT 32
#define N_EDGES 2000000
#define EPS 1e-8f
#define LMAX 96   // ELL stride; Poisson(20) max deg over 100k nodes ~47, P(>=96) ~ 1e-30

#define TB 256
#define FILL_BLOCKS ((N_EDGES / 4 + TB - 1) / TB)        // 1954 (4 edges/thread)
#define RNORM_BLOCKS ((N_NODES * 8 + TB - 1) / TB)       // 3125 (8 lanes/node)

// ---------------- scratch (static device globals; no allocs allowed) ----------------
__device__ float g_rnorm[N_NODES];          // 1/||x_n|| per node (400 KB, L2-resident)
__device__ int   g_cursor[N_NODES];         // fill cursor == in-degree after fill
__device__ int   g_ell[N_NODES * LMAX];     // ELL: src node per slot (38.4 MB)

// ---------------- packed f32x2 helpers (Blackwell packed fp32; PTX-only) ----------------
__device__ __forceinline__ uint64_t f32x2_mul(uint64_t a, uint64_t b) {
    uint64_t d; asm("mul.rn.f32x2 %0, %1, %2;" : "=l"(d) : "l"(a), "l"(b)); return d;
}
__device__ __forceinline__ uint64_t f32x2_fma(uint64_t a, uint64_t b, uint64_t c) {
    uint64_t d; asm("fma.rn.f32x2 %0, %1, %2, %3;" : "=l"(d) : "l"(a), "l"(b), "l"(c)); return d;
}
__device__ __forceinline__ uint64_t f32x2_add(uint64_t a, uint64_t b) {
    uint64_t d; asm("add.rn.f32x2 %0, %1, %2;" : "=l"(d) : "l"(a), "l"(b)); return d;
}
__device__ __forceinline__ uint64_t f32x2_pack(float lo, float hi) {
    uint64_t d; asm("mov.b64 %0, {%1, %2};" : "=l"(d) : "f"(lo), "f"(hi)); return d;
}
__device__ __forceinline__ float2 f32x2_unpack(uint64_t v) {
    float lo, hi; asm("mov.b64 {%0, %1}, %2;" : "=f"(lo), "=f"(hi) : "l"(v)); return make_float2(lo, hi);
}
__device__ __forceinline__ uint64_t shfl_xor_u64(uint64_t v, int m) {
    uint32_t lo = (uint32_t)v, hi = (uint32_t)(v >> 32);
    lo = __shfl_xor_sync(0xFFFFFFFFu, lo, m);
    hi = __shfl_xor_sync(0xFFFFFFFFu, hi, m);
    return ((uint64_t)hi << 32) | lo;
}

// ---------------- phase 1: heterogeneous rnorm + ELL fill (independent work) ----------------
__global__ void k_pre(const float* __restrict__ x,
                      const int* __restrict__ esrc,
                      const int* __restrict__ edst) {
    if (blockIdx.x < FILL_BLOCKS) {
        // ---- fill: 4 edges per thread for MLP ----
        int t  = blockIdx.x * TB + threadIdx.x;
        int e0 = t * 4;
        if (e0 >= N_EDGES) return;
        int4 d4 = __ldg((const int4*)(edst + e0));
        int4 s4 = __ldg((const int4*)(esrc + e0));
        int p0 = atomicAdd(&g_cursor[d4.x], 1);
        int p1 = atomicAdd(&g_cursor[d4.y], 1);
        int p2 = atomicAdd(&g_cursor[d4.z], 1);
        int p3 = atomicAdd(&g_cursor[d4.w], 1);
        if (p0 < LMAX) g_ell[d4.x * LMAX + p0] = s4.x;
        if (p1 < LMAX) g_ell[d4.y * LMAX + p1] = s4.y;
        if (p2 < LMAX) g_ell[d4.z * LMAX + p2] = s4.z;
        if (p3 < LMAX) g_ell[d4.w * LMAX + p3] = s4.w;
    } else {
        // ---- rnorm: 8-lane group per node ----
        int tid  = (blockIdx.x - FILL_BLOCKS) * TB + threadIdx.x;
        int node = tid >> 3;
        int gl   = tid & 7;
        if (node >= N_NODES) return;
        float4 v = __ldg((const float4*)(x + (size_t)node * D_FEAT) + gl);
        float s = v.x * v.x + v.y * v.y + v.z * v.z + v.w * v.w;
        #pragma unroll
        for (int o = 4; o; o >>= 1) s += __shfl_xor_sync(0xFFFFFFFFu, s, o);
        if (gl == 0) g_rnorm[node] = rsqrtf(s + EPS);
    }
}

// ---------------- phase 2: fused dot + exp + accumulate + normalize ----------------
// Warp per dst node; 8 edge groups of 4 lanes; lane owns 8 features (4 f32x2 pairs).
// ELL row preloaded to regs (R15); all FMA-class math uses packed f32x2 (one issue
// slot per 2 fp32 lanes) — the kernel is dynamic-issue-count bound.
// out_i = (sum_j ev_j * x_j) / (sum_j ev_j + EPS), ev_j = exp(beta * <x^_i, x^_j>).
// Max-subtraction skipped: |logit| <= 1 (beta in [0,1), cos in [-1,1]), exp in
// [0.37, 2.72]; softmax is shift-invariant (EPS scaling differs by <=1e-8 rel).
__global__ void __launch_bounds__(128, 9)
k_fused(const float* __restrict__ x,
        const float* __restrict__ beta,
        float* __restrict__ out) {
    int tid   = blockIdx.x * blockDim.x + threadIdx.x;
    int node  = tid >> 5;
    int lane  = tid & 31;
    int group = lane >> 2;       // 0..7: edge slot within iteration
    int gl    = lane & 3;        // 0..3: 8-float chunk within row
    if (node >= N_NODES) return;

    const int* ell = g_ell + (size_t)node * LMAX;
    // preload entire ELL row: slots [0,32), [32,64), [64,96)
    int i0 = __ldg(ell + lane);
    int i1 = __ldg(ell + 32 + lane);
    int i2 = __ldg(ell + 64 + lane);

    float bl2 = __ldg(beta) * 1.44269504f;               // beta * log2(e)
    float rn  = __ldg(g_rnorm + node);
    const ulonglong2* xrow = (const ulonglong2*)(x + (size_t)node * D_FEAT);
    ulonglong2 xda = __ldg(xrow + gl * 2);               // features [gl*8, gl*8+4)
    ulonglong2 xdb = __ldg(xrow + gl * 2 + 1);           // features [gl*8+4, gl*8+8)
    uint64_t rnrn = f32x2_pack(rn, rn);
    uint64_t xh0 = f32x2_mul(xda.x, rnrn);
    uint64_t xh1 = f32x2_mul(xda.y, rnrn);
    uint64_t xh2 = f32x2_mul(xdb.x, rnrn);
    uint64_t xh3 = f32x2_mul(xdb.y, rnrn);

    int deg   = min(g_cursor[node], LMAX);
    int iters = (deg + 7) >> 3;

    uint64_t acc0 = 0, acc1 = 0, acc2 = 0, acc3 = 0;     // (0.f,0.f) packed == 0ull
    float    ss   = 0.0f;

    #pragma unroll 2
    for (int it = 0; it < iters; it++) {
        int slot  = it * 8 + group;
        int valid = slot < deg;
        int reg   = it >> 2;                 // warp-uniform: which preload reg holds slot
        int hold  = (reg == 0) ? i0 : ((reg == 1) ? i1 : i2);
        int s     = __shfl_sync(0xFFFFFFFFu, hold, slot & 31);
        s = valid ? s : 0;
        const ulonglong2* srow = (const ulonglong2*)(x + (size_t)s * D_FEAT);
        ulonglong2 xsa = __ldg(srow + gl * 2);           // 2 independent 16B loads
        ulonglong2 xsb = __ldg(srow + gl * 2 + 1);
        float rs = __ldg(g_rnorm + s);
        // packed dot: 1 mul + 3 fma (vs 8 scalar FFMA)
        uint64_t pp = f32x2_mul(xh0, xsa.x);
        pp = f32x2_fma(xh1, xsa.y, pp);
        pp = f32x2_fma(xh2, xsb.x, pp);
        pp = f32x2_fma(xh3, xsb.y, pp);
        float2 ph = f32x2_unpack(pp);
        float p = ph.x + ph.y;
        // reduce dot over the 4 lanes of this group (one shfl serves all 8 groups)
        p += __shfl_xor_sync(0xFFFFFFFFu, p, 1);
        p += __shfl_xor_sync(0xFFFFFFFFu, p, 2);
        float ev = valid ? exp2f(bl2 * p * rs) : 0.0f;
        uint64_t evev = f32x2_pack(ev, ev);
        // packed accumulate: 4 fma (vs 8 scalar FFMA)
        acc0 = f32x2_fma(evev, xsa.x, acc0);
        acc1 = f32x2_fma(evev, xsa.y, acc1);
        acc2 = f32x2_fma(evev, xsb.x, acc2);
        acc3 = f32x2_fma(evev, xsb.y, acc3);
        ss += ev;
    }

    // combine the 8 groups (xor 4/8/16 preserves gl = lane&3)
    #pragma unroll
    for (int o = 4; o < 32; o <<= 1) {
        acc0 = f32x2_add(acc0, shfl_xor_u64(acc0, o));
        acc1 = f32x2_add(acc1, shfl_xor_u64(acc1, o));
        acc2 = f32x2_add(acc2, shfl_xor_u64(acc2, o));
        acc3 = f32x2_add(acc3, shfl_xor_u64(acc3, o));
        ss  += __shfl_xor_sync(0xFFFFFFFFu, ss, o);
    }

    if (lane < 4) {                                      // group 0 stores the row
        float inv = 1.0f / (ss + EPS);
        uint64_t ii = f32x2_pack(inv, inv);
        ulonglong2 oa, ob;
        oa.x = f32x2_mul(acc0, ii);
        oa.y = f32x2_mul(acc1, ii);
        ob.x = f32x2_mul(acc2, ii);
        ob.y = f32x2_mul(acc3, ii);
        ulonglong2* orow = (ulonglong2*)(out + (size_t)node * D_FEAT);
        orow[gl * 2 + 0] = oa;
        orow[gl * 2 + 1] = ob;
    }
}

// ---------------- launch ----------------
extern "C" void kernel_launch(void* const* d_in, const int* in_sizes, int n_in,
                              void* d_out, int out_size) {
    const float* x    = (const float*)d_in[0];
    const float* beta = (const float*)d_in[1];
    const int*   ei   = (const int*)d_in[2];   // [2, E] row-major, int32
    const int*   esrc = ei;
    const int*   edst = ei + N_EDGES;
    float* out = (float*)d_out;

    // zero fill cursors (graph-legal memset node)
    void* cur_ptr = nullptr;
    cudaGetSymbolAddress(&cur_ptr, g_cursor);
    cudaMemsetAsync(cur_ptr, 0, N_NODES * sizeof(int));

    const int TBF = 128;
    const int gridF = (N_NODES * 32 + TBF - 1) / TBF;   // warp per node

    k_pre<<<FILL_BLOCKS + RNORM_BLOCKS, TB>>>(x, esrc, edst);
    k_fused<<<gridF, TBF>>>(x, beta, out);
}